// round 14
// baseline (speedup 1.0000x reference)
#include <cuda_runtime.h>
#include <cuda_fp16.h>
#include <math.h>
#include <stdint.h>

#define NN      50000
#define NE      800000
#define TE      (NE + NN)
#define GG      512
#define IN_DIM  128
#define HIDD    256
#define HEADS   8
#define NEG_SLOPE 0.2f
#define BN_EPS  1e-5f

#define BM 128
#define BN 128
#define BK 64
#define NPAD    50176
#define NTILES  ((NN + BM - 1) / BM)     // 391

#define ROWB   144
#define TILEB  (128 * ROWB)              // 18432
#define AO     0
#define BHO    TILEB
#define SSZ    (2 * TILEB)               // 36864
#define SMEM_TOTAL (2 * SSZ)             // 73728

// ---------------- scratch ----------------
__device__ __half d_hf[NN * HIDD];            // h (linear out) fp16 for gathers
__device__ float d_actbuf[NN * HIDD];         // fp32 activations (residual/pool)
__device__ float d_ssrc[NN * HEADS];
__device__ float d_sdst[NN * HEADS];
__device__ __half d_a16[NPAD * HIDD];         // activation fp16 (GEMM A input)
__device__ __half d_wh[3 * HIDD * HIDD];      // W^T fp16 per layer
__device__ int d_off[NN + 1];
__device__ int d_cur[NN];
__device__ int d_es[TE];

static inline int cdiv(int a, int b) { return (a + b - 1) / b; }

// ---------------- CSR build ----------------
__global__ void k_init_deg() {
    int n = blockIdx.x * blockDim.x + threadIdx.x;
    if (n < NN) d_off[n] = 1;
}
__global__ void k_count(const int* __restrict__ dst) {
    int i = blockIdx.x * blockDim.x + threadIdx.x;
    if (i < NE / 4) {
        int4 v = ((const int4*)dst)[i];
        atomicAdd(&d_off[v.x], 1);
        atomicAdd(&d_off[v.y], 1);
        atomicAdd(&d_off[v.z], 1);
        atomicAdd(&d_off[v.w], 1);
    }
}
__global__ void k_scan() {
    __shared__ int s[1024];
    const int CH = (NN + 1023) / 1024;
    int t = threadIdx.x;
    int b = t * CH;
    int e = b + CH; if (e > NN) e = NN;
    int sum = 0;
    for (int i = b; i < e && i < NN; i++) sum += d_off[i];
    s[t] = sum;
    __syncthreads();
    for (int o = 1; o < 1024; o <<= 1) {
        int v = (t >= o) ? s[t - o] : 0;
        __syncthreads();
        s[t] += v;
        __syncthreads();
    }
    int run = s[t] - sum;
    for (int i = b; i < e && i < NN; i++) {
        int c = d_off[i];
        d_off[i] = run;
        d_cur[i] = run;
        run += c;
    }
    if (t == 0) d_off[NN] = TE;
}
__global__ void k_scatter(const int* __restrict__ src, const int* __restrict__ dst) {
    int i = blockIdx.x * blockDim.x + threadIdx.x;
    if (i < NE / 4) {
        int4 sv = ((const int4*)src)[i];
        int4 dv = ((const int4*)dst)[i];
        d_es[atomicAdd(&d_cur[dv.x], 1)] = sv.x;
        d_es[atomicAdd(&d_cur[dv.y], 1)] = sv.y;
        d_es[atomicAdd(&d_cur[dv.z], 1)] = sv.z;
        d_es[atomicAdd(&d_cur[dv.w], 1)] = sv.w;
    } else {
        int n = i - NE / 4;
        if (n < NN) d_es[atomicAdd(&d_cur[n], 1)] = n;
    }
}

// ---------------- input fp16 / weight fp16 prep ----------------
__global__ void k_cvtA(const float* __restrict__ x) {
    int idx = blockIdx.x * blockDim.x + threadIdx.x;
    if (idx >= NN * IN_DIM / 4) return;
    float4 v = ((const float4*)x)[idx];
    __half2 h0 = __floats2half2_rn(v.x, v.y);
    __half2 h1 = __floats2half2_rn(v.z, v.w);
    uint2 p;
    p.x = *(uint32_t*)&h0;
    p.y = *(uint32_t*)&h1;
    *(uint2*)(d_a16 + (size_t)idx * 4) = p;
}

// W[k][n] fp32 -> d_wh[l][n][k] fp16 (transpose)
__global__ void k_prepW(const float* __restrict__ W, int K, int l) {
    int idx = blockIdx.x * blockDim.x + threadIdx.x;
    if (idx >= K * HIDD) return;
    int k = idx / HIDD, n = idx % HIDD;
    d_wh[(size_t)l * HIDD * HIDD + (size_t)n * K + k] = __float2half_rn(W[idx]);
}

// ---------------- mma helpers ----------------
__device__ __forceinline__ uint32_t cvta_s(const void* p) {
    return (uint32_t)__cvta_generic_to_shared(p);
}
__device__ __forceinline__ void cp16(uint32_t dst, const void* src) {
    asm volatile("cp.async.cg.shared.global [%0], [%1], 16;" :: "r"(dst), "l"(src));
}
__device__ __forceinline__ void mma_f16(float* d, const uint32_t* a, const uint32_t* b) {
    asm volatile(
        "mma.sync.aligned.m16n8k16.row.col.f32.f16.f16.f32 "
        "{%0,%1,%2,%3}, {%4,%5,%6,%7}, {%8,%9}, {%0,%1,%2,%3};"
        : "+f"(d[0]), "+f"(d[1]), "+f"(d[2]), "+f"(d[3])
        : "r"(a[0]), "r"(a[1]), "r"(a[2]), "r"(a[3]), "r"(b[0]), "r"(b[1]));
}
__device__ __forceinline__ void ldm_x4(uint32_t* r, uint32_t addr) {
    asm volatile("ldmatrix.sync.aligned.m8n8.x4.shared.b16 {%0,%1,%2,%3}, [%4];"
                 : "=r"(r[0]), "=r"(r[1]), "=r"(r[2]), "=r"(r[3]) : "r"(addr));
}

__device__ __forceinline__ void stage_load(uint32_t sb, int bm0, int bn0, int K,
                                           int k0, int tid, size_t woff) {
#pragma unroll
    for (int i = 0; i < 4; i++) {
        int gg = tid + i * 256;
        int r = gg >> 3, kk = (gg & 7) * 8;
        uint32_t d = sb + (uint32_t)r * ROWB + (uint32_t)kk * 2;
        size_t soA = (size_t)(bm0 + r) * K + k0 + kk;
        size_t soB = woff + (size_t)(bn0 + r) * K + k0 + kk;
        cp16(d + AO, d_a16 + soA);
        cp16(d + BHO, d_wh + soB);
    }
    asm volatile("cp.async.commit_group;" ::: "memory");
}

// ---------------- fp16 tensor-core GEMM + fused scores ----------------
__global__ void __launch_bounds__(256, 2) k_gemm_mma(int K, int l,
                                                     const float* __restrict__ asrc,
                                                     const float* __restrict__ adst) {
    extern __shared__ char smem[];
    uint32_t sbase = cvta_s(smem);
    int tid = threadIdx.x, w = tid >> 5, lane = tid & 31;
    int bm0 = blockIdx.x * BM, bn0 = blockIdx.y * BN;
    int wm = w >> 1, wn = w & 1;
    int nch = K / BK;
    size_t woff = (size_t)l * HIDD * HIDD;

    float acc[2][8][4];
#pragma unroll
    for (int mt = 0; mt < 2; mt++)
#pragma unroll
        for (int nt = 0; nt < 8; nt++)
#pragma unroll
            for (int j = 0; j < 4; j++) acc[mt][nt][j] = 0.f;

    stage_load(sbase, bm0, bn0, K, 0, tid, woff);

    uint32_t t8 = (uint32_t)(lane >> 3), r8 = (uint32_t)(lane & 7);

    for (int c = 0; c < nch; c++) {
        if (c + 1 < nch) {
            stage_load(sbase + ((c + 1) & 1) * SSZ, bm0, bn0, K, (c + 1) * BK, tid, woff);
            asm volatile("cp.async.wait_group 1;" ::: "memory");
        } else {
            asm volatile("cp.async.wait_group 0;" ::: "memory");
        }
        __syncthreads();

        uint32_t stage = sbase + (c & 1) * SSZ;
#pragma unroll
        for (int ks = 0; ks < 4; ks++) {
            uint32_t kof = (uint32_t)ks * 32 + (t8 >> 1) * 16;
            uint32_t a_f[2][4];
#pragma unroll
            for (int mt = 0; mt < 2; mt++) {
                uint32_t arow = (uint32_t)(wm * 32 + mt * 16) + (t8 & 1) * 8 + r8;
                ldm_x4(a_f[mt], stage + AO + arow * ROWB + kof);
            }
            uint32_t kofb = (uint32_t)ks * 32 + (t8 & 1) * 16;
#pragma unroll
            for (int ntp = 0; ntp < 4; ntp++) {
                uint32_t nrow = (uint32_t)(wn * 64 + ntp * 16) + (t8 >> 1) * 8 + r8;
                uint32_t b_h[4];
                ldm_x4(b_h, stage + BHO + nrow * ROWB + kofb);
#pragma unroll
                for (int mt = 0; mt < 2; mt++) {
                    mma_f16(acc[mt][2 * ntp],     a_f[mt], b_h);
                    mma_f16(acc[mt][2 * ntp + 1], a_f[mt], b_h + 2);
                }
            }
        }
        __syncthreads();
    }

    // ---- fused attention scores ----
    float ss[2][2][2], sd[2][2][2];
#pragma unroll
    for (int mt = 0; mt < 2; mt++)
#pragma unroll
        for (int ro = 0; ro < 2; ro++)
#pragma unroll
            for (int hh = 0; hh < 2; hh++) { ss[mt][ro][hh] = 0.f; sd[mt][ro][hh] = 0.f; }

#pragma unroll
    for (int nt = 0; nt < 8; nt++) {
        int cc = bn0 + wn * 64 + nt * 8 + (lane & 3) * 2;
        float a0s = __ldg(asrc + cc), a1s = __ldg(asrc + cc + 1);
        float a0d = __ldg(adst + cc), a1d = __ldg(adst + cc + 1);
        int hh = nt >> 2;
#pragma unroll
        for (int mt = 0; mt < 2; mt++) {
            ss[mt][0][hh] += acc[mt][nt][0] * a0s + acc[mt][nt][1] * a1s;
            sd[mt][0][hh] += acc[mt][nt][0] * a0d + acc[mt][nt][1] * a1d;
            ss[mt][1][hh] += acc[mt][nt][2] * a0s + acc[mt][nt][3] * a1s;
            sd[mt][1][hh] += acc[mt][nt][2] * a0d + acc[mt][nt][3] * a1d;
        }
    }
#pragma unroll
    for (int mt = 0; mt < 2; mt++)
#pragma unroll
        for (int ro = 0; ro < 2; ro++)
#pragma unroll
            for (int hh = 0; hh < 2; hh++) {
                float vs = ss[mt][ro][hh], vd = sd[mt][ro][hh];
                vs += __shfl_xor_sync(~0u, vs, 1); vs += __shfl_xor_sync(~0u, vs, 2);
                vd += __shfl_xor_sync(~0u, vd, 1); vd += __shfl_xor_sync(~0u, vd, 2);
                if ((lane & 3) == 0) {
                    int r = bm0 + wm * 32 + mt * 16 + (lane >> 2) + ro * 8;
                    int h = (bn0 + wn * 64) / 32 + hh;
                    if (r < NN) {
                        d_ssrc[r * 8 + h] = vs;
                        d_sdst[r * 8 + h] = vd;
                    }
                }
            }

    // ---- write h as fp16 ----
#pragma unroll
    for (int mt = 0; mt < 2; mt++) {
        int r = bm0 + wm * 32 + mt * 16 + (lane >> 2);
#pragma unroll
        for (int nt = 0; nt < 8; nt++) {
            int cc = bn0 + wn * 64 + nt * 8 + (lane & 3) * 2;
            if (r < NN)
                *(__half2*)(d_hf + (size_t)r * 256 + cc) =
                    __floats2half2_rn(acc[mt][nt][0], acc[mt][nt][1]);
            if (r + 8 < NN)
                *(__half2*)(d_hf + (size_t)(r + 8) * 256 + cc) =
                    __floats2half2_rn(acc[mt][nt][2], acc[mt][nt][3]);
        }
    }
}

__device__ __forceinline__ float leaky(float x) { return x > 0.f ? x : NEG_SLOPE * x; }

// ---------------- aggregation: 2 warps / node (128 cols each), single pass ----------------
__global__ void __launch_bounds__(128) k_agg(const float* __restrict__ bias,
                      const float* __restrict__ gam,
                      const float* __restrict__ bet, const float* __restrict__ mu,
                      const float* __restrict__ var, int useRes, int storeA16) {
    int gw = (blockIdx.x * blockDim.x + threadIdx.x) >> 5;
    int lane = threadIdx.x & 31;
    int n = gw >> 1, half = gw & 1;
    if (n >= NN) return;
    int beg = d_off[n], end = d_off[n + 1];
    int h = half * 4 + (lane >> 3);          // 8 lanes per head; 4 heads per warp

    float my_sd = __ldg(d_sdst + n * 8 + h);

    // single pass: softmax denominator + weighted gather (uint2 = 4 cols per lane)
    const uint2* hf2 = (const uint2*)d_hf;   // 64 uint2 per row
    size_t rbase = (size_t)half * 32 + lane; // within-row offset
    float acc[4] = {0.f, 0.f, 0.f, 0.f};
    float z = 0.f;
    int e0 = beg;
    for (; e0 + 4 <= end; e0 += 4) {
        int s0 = d_es[e0],     s1 = d_es[e0 + 1];
        int s2 = d_es[e0 + 2], s3 = d_es[e0 + 3];
        float sv0 = __ldg(d_ssrc + s0 * 8 + h);
        float sv1 = __ldg(d_ssrc + s1 * 8 + h);
        float sv2 = __ldg(d_ssrc + s2 * 8 + h);
        float sv3 = __ldg(d_ssrc + s3 * 8 + h);
        uint2 v0 = __ldg(hf2 + (size_t)s0 * 64 + rbase);
        uint2 v1 = __ldg(hf2 + (size_t)s1 * 64 + rbase);
        uint2 v2 = __ldg(hf2 + (size_t)s2 * 64 + rbase);
        uint2 v3 = __ldg(hf2 + (size_t)s3 * 64 + rbase);
        float c0 = __expf(leaky(sv0 + my_sd));
        float c1 = __expf(leaky(sv1 + my_sd));
        float c2 = __expf(leaky(sv2 + my_sd));
        float c3 = __expf(leaky(sv3 + my_sd));
        z += c0 + c1 + c2 + c3;
        const uint2* vp[4] = {&v0, &v1, &v2, &v3};
        float cf[4] = {c0, c1, c2, c3};
#pragma unroll
        for (int j = 0; j < 4; j++) {
            uint2 v = *vp[j];
            float coef = cf[j];
            float2 f0 = __half22float2(*(const __half2*)&v.x);
            float2 f1 = __half22float2(*(const __half2*)&v.y);
            acc[0] += f0.x * coef; acc[1] += f0.y * coef;
            acc[2] += f1.x * coef; acc[3] += f1.y * coef;
        }
    }
    for (; e0 < end; e0++) {
        int s = d_es[e0];
        float sv = __ldg(d_ssrc + s * 8 + h);
        float coef = __expf(leaky(sv + my_sd));
        z += coef;
        uint2 v = __ldg(hf2 + (size_t)s * 64 + rbase);
        float2 f0 = __half22float2(*(const __half2*)&v.x);
        float2 f1 = __half22float2(*(const __half2*)&v.y);
        acc[0] += f0.x * coef; acc[1] += f0.y * coef;
        acc[2] += f1.x * coef; acc[3] += f1.y * coef;
    }
    float inv = 1.f / (z + 1e-16f);
#pragma unroll
    for (int j = 0; j < 4; j++) acc[j] *= inv;

    // epilogue: cols col..col+3
    int col = half * 128 + lane * 4;
    float4 bb4 = *(const float4*)(bias + col);
    float4 gg4 = *(const float4*)(gam + col);
    float4 ee4 = *(const float4*)(bet + col);
    float4 uu4 = *(const float4*)(mu + col);
    float4 vv4 = *(const float4*)(var + col);
    float4* act4 = (float4*)d_actbuf;
    int aidx = n * 64 + half * 32 + lane;
    float4 rr4 = make_float4(0.f, 0.f, 0.f, 0.f);
    if (useRes) rr4 = act4[aidx];
    float bb[4] = {bb4.x, bb4.y, bb4.z, bb4.w};
    float gg[4] = {gg4.x, gg4.y, gg4.z, gg4.w};
    float ee[4] = {ee4.x, ee4.y, ee4.z, ee4.w};
    float uu[4] = {uu4.x, uu4.y, uu4.z, uu4.w};
    float vv[4] = {vv4.x, vv4.y, vv4.z, vv4.w};
    float rr[4] = {rr4.x, rr4.y, rr4.z, rr4.w};
    float outv[4];
#pragma unroll
    for (int j = 0; j < 4; j++) {
        float v = acc[j] + bb[j];
        v = (v - uu[j]) * rsqrtf(vv[j] + BN_EPS) * gg[j] + ee[j];
        if (useRes) v += rr[j];
        outv[j] = v > 0.f ? v : (__expf(v) - 1.0f);
    }
    act4[aidx] = make_float4(outv[0], outv[1], outv[2], outv[3]);

    if (storeA16) {
        __half2 q0 = __floats2half2_rn(outv[0], outv[1]);
        __half2 q1 = __floats2half2_rn(outv[2], outv[3]);
        uint2 pk;
        pk.x = *(uint32_t*)&q0;
        pk.y = *(uint32_t*)&q1;
        *(uint2*)(d_a16 + (size_t)n * 256 + col) = pk;
    }
}

// ---------------- pooling + output heads ----------------
__device__ __forceinline__ int lbound(const int* __restrict__ a, int n, int v) {
    int lo = 0, hi = n;
    while (lo < hi) {
        int mid = (lo + hi) >> 1;
        if (a[mid] < v) lo = mid + 1; else hi = mid;
    }
    return lo;
}

__global__ void k_pool(const int* __restrict__ batch,
                       const float* __restrict__ ow0, const float* __restrict__ ob0,
                       const float* __restrict__ ow1, const float* __restrict__ ob1,
                       float* __restrict__ out) {
    int g = blockIdx.x;
    int t = threadIdx.x;
    int lo = lbound(batch, NN, g);
    int hi = lbound(batch, NN, g + 1);
    __shared__ float pooled[3 * HIDD];
    __shared__ float sacc[6];

    int c = t;
    float sum = 0.f, mx = -1e30f;
    for (int n = lo; n < hi; n++) {
        float v = d_actbuf[(size_t)n * 256 + c];
        sum += v;
        mx = fmaxf(mx, v);
    }
    int cnt = hi - lo;
    pooled[c]       = sum / fmaxf((float)cnt, 1.f);
    pooled[256 + c] = sum;
    pooled[512 + c] = (cnt > 0) ? mx : 0.f;
    if (t < 6) sacc[t] = 0.f;
    __syncthreads();

    float p0[3] = {0.f, 0.f, 0.f}, p1[3] = {0.f, 0.f, 0.f};
    for (int j = t; j < 768; j += 256) {
        float v = pooled[j];
#pragma unroll
        for (int k = 0; k < 3; k++) {
            p0[k] += v * ow0[j * 3 + k];
            p1[k] += v * ow1[j * 3 + k];
        }
    }
#pragma unroll
    for (int k = 0; k < 3; k++) {
        atomicAdd(&sacc[k], p0[k]);
        atomicAdd(&sacc[3 + k], p1[k]);
    }
    __syncthreads();
    if (t < 3) {
        out[g * 3 + t]          = sacc[t]     + ob0[t];
        out[GG * 3 + g * 3 + t] = sacc[3 + t] + ob1[t];
    }
}

// ---------------- launch ----------------
extern "C" void kernel_launch(void* const* d_in, const int* in_sizes, int n_in,
                              void* d_out, int out_size) {
    const float* x     = (const float*)d_in[0];
    const int*   ei    = (const int*)d_in[1];
    const int*   batch = (const int*)d_in[2];

    const float* W[3]  = {(const float*)d_in[3],  (const float*)d_in[11], (const float*)d_in[19]};
    const float* AS[3] = {(const float*)d_in[4],  (const float*)d_in[12], (const float*)d_in[20]};
    const float* AD[3] = {(const float*)d_in[5],  (const float*)d_in[13], (const float*)d_in[21]};
    const float* BI[3] = {(const float*)d_in[6],  (const float*)d_in[14], (const float*)d_in[22]};
    const float* GA[3] = {(const float*)d_in[7],  (const float*)d_in[15], (const float*)d_in[23]};
    const float* BE[3] = {(const float*)d_in[8],  (const float*)d_in[16], (const float*)d_in[24]};
    const float* MU[3] = {(const float*)d_in[9],  (const float*)d_in[17], (const float*)d_in[25]};
    const float* VA[3] = {(const float*)d_in[10], (const float*)d_in[18], (const float*)d_in[26]};
    const float* ow0 = (const float*)d_in[27];
    const float* ob0 = (const float*)d_in[28];
    const float* ow1 = (const float*)d_in[29];
    const float* ob1 = (const float*)d_in[30];
    float* out = (float*)d_out;

    static cudaStream_t s2 = nullptr;
    static cudaEvent_t evA = nullptr, evB = nullptr;
    if (!s2) {
        cudaFuncSetAttribute(k_gemm_mma, cudaFuncAttributeMaxDynamicSharedMemorySize,
                             SMEM_TOTAL);
        cudaStreamCreateWithFlags(&s2, cudaStreamNonBlocking);
        cudaEventCreateWithFlags(&evA, cudaEventDisableTiming);
        cudaEventCreateWithFlags(&evB, cudaEventDisableTiming);
    }

    // Fork: CSR build + layer-2/3 weight prep on s2, overlapped with the
    // critical path (prepW0 + cvtA + GEMM layer 1) on the main stream.
    cudaEventRecord(evA, 0);
    cudaStreamWaitEvent(s2, evA, 0);
    k_init_deg<<<cdiv(NN, 256), 256, 0, s2>>>();
    k_count<<<cdiv(NE / 4, 256), 256, 0, s2>>>(ei + NE);
    k_scan<<<1, 1024, 0, s2>>>();
    k_scatter<<<cdiv(NE / 4 + NN, 256), 256, 0, s2>>>(ei, ei + NE);
    k_prepW<<<cdiv(HIDD * HIDD, 256), 256, 0, s2>>>(W[1], HIDD, 1);
    k_prepW<<<cdiv(HIDD * HIDD, 256), 256, 0, s2>>>(W[2], HIDD, 2);
    cudaEventRecord(evB, s2);

    k_prepW<<<cdiv(IN_DIM * HIDD, 256), 256>>>(W[0], IN_DIM, 0);
    k_cvtA<<<cdiv(NN * IN_DIM / 4, 256), 256>>>(x);

    dim3 gg(NTILES, 2);
    k_gemm_mma<<<gg, 256, SMEM_TOTAL>>>(IN_DIM, 0, AS[0], AD[0]);

    // Join: aggregation needs the CSR (and later GEMMs need W1/W2).
    cudaStreamWaitEvent(0, evB, 0);

    k_agg<<<cdiv(NN * 2, 4), 128>>>(BI[0], GA[0], BE[0], MU[0], VA[0], 0, 1);
    for (int l = 1; l < 3; l++) {
        k_gemm_mma<<<gg, 256, SMEM_TOTAL>>>(HIDD, l, AS[l], AD[l]);
        k_agg<<<cdiv(NN * 2, 4), 128>>>(BI[l], GA[l], BE[l], MU[l], VA[l], 1, l < 2 ? 1 : 0);
    }
    k_pool<<<GG, 256>>>(batch, ow0, ob0, ow1, ob1, out);
}

// round 15
// speedup vs baseline: 1.1145x; 1.1145x over previous
#include <cuda_runtime.h>
#include <cuda_fp16.h>
#include <math.h>
#include <stdint.h>

#define NN      50000
#define NE      800000
#define TE      (NE + NN)
#define GG      512
#define IN_DIM  128
#define HIDD    256
#define HEADS   8
#define NEG_SLOPE 0.2f
#define BN_EPS  1e-5f

#define BM 128
#define BN 128
#define BK 64
#define NPAD    50176
#define NTILES  ((NN + BM - 1) / BM)     // 391

#define ROWB   144
#define TILEB  (128 * ROWB)              // 18432
#define AO     0
#define BHO    TILEB
#define SSZ    (2 * TILEB)               // 36864
#define SMEM_TOTAL (2 * SSZ)             // 73728

// ---------------- scratch ----------------
__device__ __half d_hf[NN * HIDD];            // h (linear out) fp16 for gathers
__device__ float d_actbuf[NN * HIDD];         // fp32 activations (residual/pool)
__device__ float d_ssrc[NN * HEADS];
__device__ float d_sdst[NN * HEADS];
__device__ __half d_a16[NPAD * HIDD];         // activation fp16 (GEMM A input)
__device__ __half d_wh[3 * HIDD * HIDD];      // W^T fp16 per layer
__device__ int d_off[NN + 1];
__device__ int d_cur[NN];
__device__ int d_es[TE];

static inline int cdiv(int a, int b) { return (a + b - 1) / b; }

// ---------------- CSR build ----------------
__global__ void k_init_deg() {
    int n = blockIdx.x * blockDim.x + threadIdx.x;
    if (n < NN) d_off[n] = 1;
}
__global__ void k_count(const int* __restrict__ dst) {
    int i = blockIdx.x * blockDim.x + threadIdx.x;
    if (i < NE / 4) {
        int4 v = ((const int4*)dst)[i];
        atomicAdd(&d_off[v.x], 1);
        atomicAdd(&d_off[v.y], 1);
        atomicAdd(&d_off[v.z], 1);
        atomicAdd(&d_off[v.w], 1);
    }
}
__global__ void k_scan() {
    __shared__ int s[1024];
    const int CH = (NN + 1023) / 1024;
    int t = threadIdx.x;
    int b = t * CH;
    int e = b + CH; if (e > NN) e = NN;
    int sum = 0;
    for (int i = b; i < e && i < NN; i++) sum += d_off[i];
    s[t] = sum;
    __syncthreads();
    for (int o = 1; o < 1024; o <<= 1) {
        int v = (t >= o) ? s[t - o] : 0;
        __syncthreads();
        s[t] += v;
        __syncthreads();
    }
    int run = s[t] - sum;
    for (int i = b; i < e && i < NN; i++) {
        int c = d_off[i];
        d_off[i] = run;
        d_cur[i] = run;
        run += c;
    }
    if (t == 0) d_off[NN] = TE;
}
__global__ void k_scatter(const int* __restrict__ src, const int* __restrict__ dst) {
    int i = blockIdx.x * blockDim.x + threadIdx.x;
    if (i < NE / 4) {
        int4 sv = ((const int4*)src)[i];
        int4 dv = ((const int4*)dst)[i];
        d_es[atomicAdd(&d_cur[dv.x], 1)] = sv.x;
        d_es[atomicAdd(&d_cur[dv.y], 1)] = sv.y;
        d_es[atomicAdd(&d_cur[dv.z], 1)] = sv.z;
        d_es[atomicAdd(&d_cur[dv.w], 1)] = sv.w;
    } else {
        int n = i - NE / 4;
        if (n < NN) d_es[atomicAdd(&d_cur[n], 1)] = n;
    }
}

// ---------------- input fp16 / weight fp16 prep ----------------
__global__ void k_cvtA(const float* __restrict__ x) {
    int idx = blockIdx.x * blockDim.x + threadIdx.x;
    if (idx >= NN * IN_DIM / 4) return;
    float4 v = ((const float4*)x)[idx];
    __half2 h0 = __floats2half2_rn(v.x, v.y);
    __half2 h1 = __floats2half2_rn(v.z, v.w);
    uint2 p;
    p.x = *(uint32_t*)&h0;
    p.y = *(uint32_t*)&h1;
    *(uint2*)(d_a16 + (size_t)idx * 4) = p;
}

// W[k][n] fp32 -> d_wh[l][n][k] fp16 (transpose)
__global__ void k_prepW(const float* __restrict__ W, int K, int l) {
    int idx = blockIdx.x * blockDim.x + threadIdx.x;
    if (idx >= K * HIDD) return;
    int k = idx / HIDD, n = idx % HIDD;
    d_wh[(size_t)l * HIDD * HIDD + (size_t)n * K + k] = __float2half_rn(W[idx]);
}

// ---------------- mma helpers ----------------
__device__ __forceinline__ uint32_t cvta_s(const void* p) {
    return (uint32_t)__cvta_generic_to_shared(p);
}
__device__ __forceinline__ void cp16(uint32_t dst, const void* src) {
    asm volatile("cp.async.cg.shared.global [%0], [%1], 16;" :: "r"(dst), "l"(src));
}
__device__ __forceinline__ void mma_f16(float* d, const uint32_t* a, const uint32_t* b) {
    asm volatile(
        "mma.sync.aligned.m16n8k16.row.col.f32.f16.f16.f32 "
        "{%0,%1,%2,%3}, {%4,%5,%6,%7}, {%8,%9}, {%0,%1,%2,%3};"
        : "+f"(d[0]), "+f"(d[1]), "+f"(d[2]), "+f"(d[3])
        : "r"(a[0]), "r"(a[1]), "r"(a[2]), "r"(a[3]), "r"(b[0]), "r"(b[1]));
}
__device__ __forceinline__ void ldm_x4(uint32_t* r, uint32_t addr) {
    asm volatile("ldmatrix.sync.aligned.m8n8.x4.shared.b16 {%0,%1,%2,%3}, [%4];"
                 : "=r"(r[0]), "=r"(r[1]), "=r"(r[2]), "=r"(r[3]) : "r"(addr));
}

__device__ __forceinline__ void stage_load(uint32_t sb, int bm0, int bn0, int K,
                                           int k0, int tid, size_t woff) {
#pragma unroll
    for (int i = 0; i < 4; i++) {
        int gg = tid + i * 256;
        int r = gg >> 3, kk = (gg & 7) * 8;
        uint32_t d = sb + (uint32_t)r * ROWB + (uint32_t)kk * 2;
        size_t soA = (size_t)(bm0 + r) * K + k0 + kk;
        size_t soB = woff + (size_t)(bn0 + r) * K + k0 + kk;
        cp16(d + AO, d_a16 + soA);
        cp16(d + BHO, d_wh + soB);
    }
    asm volatile("cp.async.commit_group;" ::: "memory");
}

// ---------------- fp16 tensor-core GEMM + fused scores ----------------
__global__ void __launch_bounds__(256, 2) k_gemm_mma(int K, int l,
                                                     const float* __restrict__ asrc,
                                                     const float* __restrict__ adst) {
    extern __shared__ char smem[];
    uint32_t sbase = cvta_s(smem);
    int tid = threadIdx.x, w = tid >> 5, lane = tid & 31;
    int bm0 = blockIdx.x * BM, bn0 = blockIdx.y * BN;
    int wm = w >> 1, wn = w & 1;
    int nch = K / BK;
    size_t woff = (size_t)l * HIDD * HIDD;

    float acc[2][8][4];
#pragma unroll
    for (int mt = 0; mt < 2; mt++)
#pragma unroll
        for (int nt = 0; nt < 8; nt++)
#pragma unroll
            for (int j = 0; j < 4; j++) acc[mt][nt][j] = 0.f;

    stage_load(sbase, bm0, bn0, K, 0, tid, woff);

    uint32_t t8 = (uint32_t)(lane >> 3), r8 = (uint32_t)(lane & 7);

    for (int c = 0; c < nch; c++) {
        if (c + 1 < nch) {
            stage_load(sbase + ((c + 1) & 1) * SSZ, bm0, bn0, K, (c + 1) * BK, tid, woff);
            asm volatile("cp.async.wait_group 1;" ::: "memory");
        } else {
            asm volatile("cp.async.wait_group 0;" ::: "memory");
        }
        __syncthreads();

        uint32_t stage = sbase + (c & 1) * SSZ;
#pragma unroll
        for (int ks = 0; ks < 4; ks++) {
            uint32_t kof = (uint32_t)ks * 32 + (t8 >> 1) * 16;
            uint32_t a_f[2][4];
#pragma unroll
            for (int mt = 0; mt < 2; mt++) {
                uint32_t arow = (uint32_t)(wm * 32 + mt * 16) + (t8 & 1) * 8 + r8;
                ldm_x4(a_f[mt], stage + AO + arow * ROWB + kof);
            }
            uint32_t kofb = (uint32_t)ks * 32 + (t8 & 1) * 16;
#pragma unroll
            for (int ntp = 0; ntp < 4; ntp++) {
                uint32_t nrow = (uint32_t)(wn * 64 + ntp * 16) + (t8 >> 1) * 8 + r8;
                uint32_t b_h[4];
                ldm_x4(b_h, stage + BHO + nrow * ROWB + kofb);
#pragma unroll
                for (int mt = 0; mt < 2; mt++) {
                    mma_f16(acc[mt][2 * ntp],     a_f[mt], b_h);
                    mma_f16(acc[mt][2 * ntp + 1], a_f[mt], b_h + 2);
                }
            }
        }
        __syncthreads();
    }

    // ---- fused attention scores ----
    float ss[2][2][2], sd[2][2][2];
#pragma unroll
    for (int mt = 0; mt < 2; mt++)
#pragma unroll
        for (int ro = 0; ro < 2; ro++)
#pragma unroll
            for (int hh = 0; hh < 2; hh++) { ss[mt][ro][hh] = 0.f; sd[mt][ro][hh] = 0.f; }

#pragma unroll
    for (int nt = 0; nt < 8; nt++) {
        int cc = bn0 + wn * 64 + nt * 8 + (lane & 3) * 2;
        float a0s = __ldg(asrc + cc), a1s = __ldg(asrc + cc + 1);
        float a0d = __ldg(adst + cc), a1d = __ldg(adst + cc + 1);
        int hh = nt >> 2;
#pragma unroll
        for (int mt = 0; mt < 2; mt++) {
            ss[mt][0][hh] += acc[mt][nt][0] * a0s + acc[mt][nt][1] * a1s;
            sd[mt][0][hh] += acc[mt][nt][0] * a0d + acc[mt][nt][1] * a1d;
            ss[mt][1][hh] += acc[mt][nt][2] * a0s + acc[mt][nt][3] * a1s;
            sd[mt][1][hh] += acc[mt][nt][2] * a0d + acc[mt][nt][3] * a1d;
        }
    }
#pragma unroll
    for (int mt = 0; mt < 2; mt++)
#pragma unroll
        for (int ro = 0; ro < 2; ro++)
#pragma unroll
            for (int hh = 0; hh < 2; hh++) {
                float vs = ss[mt][ro][hh], vd = sd[mt][ro][hh];
                vs += __shfl_xor_sync(~0u, vs, 1); vs += __shfl_xor_sync(~0u, vs, 2);
                vd += __shfl_xor_sync(~0u, vd, 1); vd += __shfl_xor_sync(~0u, vd, 2);
                if ((lane & 3) == 0) {
                    int r = bm0 + wm * 32 + mt * 16 + (lane >> 2) + ro * 8;
                    int h = (bn0 + wn * 64) / 32 + hh;
                    if (r < NN) {
                        d_ssrc[r * 8 + h] = vs;
                        d_sdst[r * 8 + h] = vd;
                    }
                }
            }

    // ---- write h as fp16 ----
#pragma unroll
    for (int mt = 0; mt < 2; mt++) {
        int r = bm0 + wm * 32 + mt * 16 + (lane >> 2);
#pragma unroll
        for (int nt = 0; nt < 8; nt++) {
            int cc = bn0 + wn * 64 + nt * 8 + (lane & 3) * 2;
            if (r < NN)
                *(__half2*)(d_hf + (size_t)r * 256 + cc) =
                    __floats2half2_rn(acc[mt][nt][0], acc[mt][nt][1]);
            if (r + 8 < NN)
                *(__half2*)(d_hf + (size_t)(r + 8) * 256 + cc) =
                    __floats2half2_rn(acc[mt][nt][2], acc[mt][nt][3]);
        }
    }
}

__device__ __forceinline__ float leaky(float x) { return x > 0.f ? x : NEG_SLOPE * x; }

// ---------------- aggregation (1 warp / node), single pass, 8-deep pipeline ----------------
__global__ void __launch_bounds__(128) k_agg(const float* __restrict__ bias,
                      const float* __restrict__ gam,
                      const float* __restrict__ bet, const float* __restrict__ mu,
                      const float* __restrict__ var, int useRes, int storeA16) {
    int warp = (blockIdx.x * blockDim.x + threadIdx.x) >> 5;
    int lane = threadIdx.x & 31;
    if (warp >= NN) return;
    int n = warp;
    int beg = d_off[n], end = d_off[n + 1];
    int h = lane >> 2;

    float my_sd = __ldg(d_sdst + n * 8 + h);

    const uint4* hf4 = (const uint4*)d_hf;
    float acc[8] = {0.f, 0.f, 0.f, 0.f, 0.f, 0.f, 0.f, 0.f};
    float z = 0.f;
    int e0 = beg;
    for (; e0 + 8 <= end; e0 += 8) {
        int s[8];
#pragma unroll
        for (int j = 0; j < 8; j++) s[j] = d_es[e0 + j];
        float sv[8];
#pragma unroll
        for (int j = 0; j < 8; j++) sv[j] = __ldg(d_ssrc + s[j] * 8 + h);
        uint4 v[8];
#pragma unroll
        for (int j = 0; j < 8; j++) v[j] = __ldg(hf4 + (size_t)s[j] * 32 + lane);
        float cf[8];
#pragma unroll
        for (int j = 0; j < 8; j++) {
            cf[j] = __expf(leaky(sv[j] + my_sd));
            z += cf[j];
        }
#pragma unroll
        for (int j = 0; j < 8; j++) {
            float coef = cf[j];
            float2 f0 = __half22float2(*(const __half2*)&v[j].x);
            float2 f1 = __half22float2(*(const __half2*)&v[j].y);
            float2 f2 = __half22float2(*(const __half2*)&v[j].z);
            float2 f3 = __half22float2(*(const __half2*)&v[j].w);
            acc[0] += f0.x * coef; acc[1] += f0.y * coef;
            acc[2] += f1.x * coef; acc[3] += f1.y * coef;
            acc[4] += f2.x * coef; acc[5] += f2.y * coef;
            acc[6] += f3.x * coef; acc[7] += f3.y * coef;
        }
    }
    for (; e0 < end; e0++) {
        int s = d_es[e0];
        float sv = __ldg(d_ssrc + s * 8 + h);
        float coef = __expf(leaky(sv + my_sd));
        z += coef;
        uint4 v = __ldg(hf4 + (size_t)s * 32 + lane);
        float2 f0 = __half22float2(*(const __half2*)&v.x);
        float2 f1 = __half22float2(*(const __half2*)&v.y);
        float2 f2 = __half22float2(*(const __half2*)&v.z);
        float2 f3 = __half22float2(*(const __half2*)&v.w);
        acc[0] += f0.x * coef; acc[1] += f0.y * coef;
        acc[2] += f1.x * coef; acc[3] += f1.y * coef;
        acc[4] += f2.x * coef; acc[5] += f2.y * coef;
        acc[6] += f3.x * coef; acc[7] += f3.y * coef;
    }
    float inv = 1.f / (z + 1e-16f);
#pragma unroll
    for (int j = 0; j < 8; j++) acc[j] *= inv;

    // epilogue: cols col..col+7
    int col = lane * 8;
    float4 b0 = *(const float4*)(bias + col), b1 = *(const float4*)(bias + col + 4);
    float4 g0 = *(const float4*)(gam + col),  g1 = *(const float4*)(gam + col + 4);
    float4 e0v = *(const float4*)(bet + col), e1 = *(const float4*)(bet + col + 4);
    float4 u0 = *(const float4*)(mu + col),   u1 = *(const float4*)(mu + col + 4);
    float4 w0 = *(const float4*)(var + col),  w1 = *(const float4*)(var + col + 4);
    float4* act4 = (float4*)d_actbuf;
    float4 r0 = make_float4(0.f, 0.f, 0.f, 0.f), r1 = r0;
    if (useRes) {
        r0 = act4[(size_t)n * 64 + lane * 2];
        r1 = act4[(size_t)n * 64 + lane * 2 + 1];
    }
    float bb[8] = {b0.x, b0.y, b0.z, b0.w, b1.x, b1.y, b1.z, b1.w};
    float gg[8] = {g0.x, g0.y, g0.z, g0.w, g1.x, g1.y, g1.z, g1.w};
    float ee[8] = {e0v.x, e0v.y, e0v.z, e0v.w, e1.x, e1.y, e1.z, e1.w};
    float uu[8] = {u0.x, u0.y, u0.z, u0.w, u1.x, u1.y, u1.z, u1.w};
    float vv[8] = {w0.x, w0.y, w0.z, w0.w, w1.x, w1.y, w1.z, w1.w};
    float rr[8] = {r0.x, r0.y, r0.z, r0.w, r1.x, r1.y, r1.z, r1.w};
    float outv[8];
#pragma unroll
    for (int j = 0; j < 8; j++) {
        float v = acc[j] + bb[j];
        v = (v - uu[j]) * rsqrtf(vv[j] + BN_EPS) * gg[j] + ee[j];
        if (useRes) v += rr[j];
        outv[j] = v > 0.f ? v : (__expf(v) - 1.0f);
    }
    act4[(size_t)n * 64 + lane * 2]     = make_float4(outv[0], outv[1], outv[2], outv[3]);
    act4[(size_t)n * 64 + lane * 2 + 1] = make_float4(outv[4], outv[5], outv[6], outv[7]);

    if (storeA16) {
        __half2 q0 = __floats2half2_rn(outv[0], outv[1]);
        __half2 q1 = __floats2half2_rn(outv[2], outv[3]);
        __half2 q2 = __floats2half2_rn(outv[4], outv[5]);
        __half2 q3 = __floats2half2_rn(outv[6], outv[7]);
        uint4 pk;
        pk.x = *(uint32_t*)&q0; pk.y = *(uint32_t*)&q1;
        pk.z = *(uint32_t*)&q2; pk.w = *(uint32_t*)&q3;
        *(uint4*)(d_a16 + (size_t)n * 256 + col) = pk;
    }
}

// ---------------- pooling + output heads ----------------
__device__ __forceinline__ int lbound(const int* __restrict__ a, int n, int v) {
    int lo = 0, hi = n;
    while (lo < hi) {
        int mid = (lo + hi) >> 1;
        if (a[mid] < v) lo = mid + 1; else hi = mid;
    }
    return lo;
}

__global__ void k_pool(const int* __restrict__ batch,
                       const float* __restrict__ ow0, const float* __restrict__ ob0,
                       const float* __restrict__ ow1, const float* __restrict__ ob1,
                       float* __restrict__ out) {
    int g = blockIdx.x;
    int t = threadIdx.x;
    int lo = lbound(batch, NN, g);
    int hi = lbound(batch, NN, g + 1);
    __shared__ float pooled[3 * HIDD];
    __shared__ float sacc[6];

    int c = t;
    float sum = 0.f, mx = -1e30f;
    for (int n = lo; n < hi; n++) {
        float v = d_actbuf[(size_t)n * 256 + c];
        sum += v;
        mx = fmaxf(mx, v);
    }
    int cnt = hi - lo;
    pooled[c]       = sum / fmaxf((float)cnt, 1.f);
    pooled[256 + c] = sum;
    pooled[512 + c] = (cnt > 0) ? mx : 0.f;
    if (t < 6) sacc[t] = 0.f;
    __syncthreads();

    float p0[3] = {0.f, 0.f, 0.f}, p1[3] = {0.f, 0.f, 0.f};
    for (int j = t; j < 768; j += 256) {
        float v = pooled[j];
#pragma unroll
        for (int k = 0; k < 3; k++) {
            p0[k] += v * ow0[j * 3 + k];
            p1[k] += v * ow1[j * 3 + k];
        }
    }
#pragma unroll
    for (int k = 0; k < 3; k++) {
        atomicAdd(&sacc[k], p0[k]);
        atomicAdd(&sacc[3 + k], p1[k]);
    }
    __syncthreads();
    if (t < 3) {
        out[g * 3 + t]          = sacc[t]     + ob0[t];
        out[GG * 3 + g * 3 + t] = sacc[3 + t] + ob1[t];
    }
}

// ---------------- launch ----------------
extern "C" void kernel_launch(void* const* d_in, const int* in_sizes, int n_in,
                              void* d_out, int out_size) {
    const float* x     = (const float*)d_in[0];
    const int*   ei    = (const int*)d_in[1];
    const int*   batch = (const int*)d_in[2];

    const float* W[3]  = {(const float*)d_in[3],  (const float*)d_in[11], (const float*)d_in[19]};
    const float* AS[3] = {(const float*)d_in[4],  (const float*)d_in[12], (const float*)d_in[20]};
    const float* AD[3] = {(const float*)d_in[5],  (const float*)d_in[13], (const float*)d_in[21]};
    const float* BI[3] = {(const float*)d_in[6],  (const float*)d_in[14], (const float*)d_in[22]};
    const float* GA[3] = {(const float*)d_in[7],  (const float*)d_in[15], (const float*)d_in[23]};
    const float* BE[3] = {(const float*)d_in[8],  (const float*)d_in[16], (const float*)d_in[24]};
    const float* MU[3] = {(const float*)d_in[9],  (const float*)d_in[17], (const float*)d_in[25]};
    const float* VA[3] = {(const float*)d_in[10], (const float*)d_in[18], (const float*)d_in[26]};
    const float* ow0 = (const float*)d_in[27];
    const float* ob0 = (const float*)d_in[28];
    const float* ow1 = (const float*)d_in[29];
    const float* ob1 = (const float*)d_in[30];
    float* out = (float*)d_out;

    static cudaStream_t s2 = nullptr;
    static cudaEvent_t evA = nullptr, evB = nullptr;
    if (!s2) {
        cudaFuncSetAttribute(k_gemm_mma, cudaFuncAttributeMaxDynamicSharedMemorySize,
                             SMEM_TOTAL);
        cudaStreamCreateWithFlags(&s2, cudaStreamNonBlocking);
        cudaEventCreateWithFlags(&evA, cudaEventDisableTiming);
        cudaEventCreateWithFlags(&evB, cudaEventDisableTiming);
    }

    // Fork: CSR build + layer-2/3 weight prep on s2, overlapped with the
    // critical path (prepW0 + cvtA + GEMM layer 1) on the main stream.
    cudaEventRecord(evA, 0);
    cudaStreamWaitEvent(s2, evA, 0);
    k_init_deg<<<cdiv(NN, 256), 256, 0, s2>>>();
    k_count<<<cdiv(NE / 4, 256), 256, 0, s2>>>(ei + NE);
    k_scan<<<1, 1024, 0, s2>>>();
    k_scatter<<<cdiv(NE / 4 + NN, 256), 256, 0, s2>>>(ei, ei + NE);
    k_prepW<<<cdiv(HIDD * HIDD, 256), 256, 0, s2>>>(W[1], HIDD, 1);
    k_prepW<<<cdiv(HIDD * HIDD, 256), 256, 0, s2>>>(W[2], HIDD, 2);
    cudaEventRecord(evB, s2);

    k_prepW<<<cdiv(IN_DIM * HIDD, 256), 256>>>(W[0], IN_DIM, 0);
    k_cvtA<<<cdiv(NN * IN_DIM / 4, 256), 256>>>(x);

    dim3 gg(NTILES, 2);
    k_gemm_mma<<<gg, 256, SMEM_TOTAL>>>(IN_DIM, 0, AS[0], AD[0]);

    // Join: aggregation needs the CSR (and later GEMMs need W1/W2).
    cudaStreamWaitEvent(0, evB, 0);

    k_agg<<<cdiv(NN, 4), 128>>>(BI[0], GA[0], BE[0], MU[0], VA[0], 0, 1);
    for (int l = 1; l < 3; l++) {
        k_gemm_mma<<<gg, 256, SMEM_TOTAL>>>(HIDD, l, AS[l], AD[l]);
        k_agg<<<cdiv(NN, 4), 128>>>(BI[l], GA[l], BE[l], MU[l], VA[l], 1, l < 2 ? 1 : 0);
    }
    k_pool<<<GG, 256>>>(batch, ow0, ob0, ow1, ob1, out);
}

// round 16
// speedup vs baseline: 1.2230x; 1.0973x over previous
#include <cuda_runtime.h>
#include <cuda_fp16.h>
#include <math.h>
#include <stdint.h>

#define NN      50000
#define NE      800000
#define TE      (NE + NN)
#define GG      512
#define IN_DIM  128
#define HIDD    256
#define HEADS   8
#define NEG_SLOPE 0.2f
#define BN_EPS  1e-5f

#define BM 128
#define BN 128
#define BK 64
#define NPAD    50176
#define NTILES  ((NN + BM - 1) / BM)     // 391

#define ROWB   144
#define TILEB  (128 * ROWB)              // 18432
#define AO     0
#define BHO    TILEB
#define SSZ    (2 * TILEB)               // 36864
#define SMEM_TOTAL (2 * SSZ)             // 73728

// ---------------- scratch ----------------
__device__ __half d_hf[NN * HIDD];            // h (linear out) fp16 for gathers
__device__ float d_ssrc[NN * HEADS];
__device__ float d_sdst[NN * HEADS];
__device__ __half d_a16[NPAD * HIDD];         // fp16 activations (GEMM A / residual / pool)
__device__ __half d_wh[3 * HIDD * HIDD];      // W^T fp16 per layer
__device__ float d_bnS[3 * HIDD];             // folded BN scale g'
__device__ float d_bnC[3 * HIDD];             // folded BN shift c
__device__ int d_off[NN + 1];
__device__ int d_cur[NN];
__device__ int d_es[TE];

static inline int cdiv(int a, int b) { return (a + b - 1) / b; }

// ---------------- CSR build ----------------
__global__ void k_init_deg() {
    int n = blockIdx.x * blockDim.x + threadIdx.x;
    if (n < NN) d_off[n] = 1;
}
__global__ void k_count(const int* __restrict__ dst) {
    int i = blockIdx.x * blockDim.x + threadIdx.x;
    if (i < NE / 4) {
        int4 v = ((const int4*)dst)[i];
        atomicAdd(&d_off[v.x], 1);
        atomicAdd(&d_off[v.y], 1);
        atomicAdd(&d_off[v.z], 1);
        atomicAdd(&d_off[v.w], 1);
    }
}
__global__ void k_scan() {
    __shared__ int s[1024];
    const int CH = (NN + 1023) / 1024;
    int t = threadIdx.x;
    int b = t * CH;
    int e = b + CH; if (e > NN) e = NN;
    int sum = 0;
    for (int i = b; i < e && i < NN; i++) sum += d_off[i];
    s[t] = sum;
    __syncthreads();
    for (int o = 1; o < 1024; o <<= 1) {
        int v = (t >= o) ? s[t - o] : 0;
        __syncthreads();
        s[t] += v;
        __syncthreads();
    }
    int run = s[t] - sum;
    for (int i = b; i < e && i < NN; i++) {
        int c = d_off[i];
        d_off[i] = run;
        d_cur[i] = run;
        run += c;
    }
    if (t == 0) d_off[NN] = TE;
}
__global__ void k_scatter(const int* __restrict__ src, const int* __restrict__ dst) {
    int i = blockIdx.x * blockDim.x + threadIdx.x;
    if (i < NE / 4) {
        int4 sv = ((const int4*)src)[i];
        int4 dv = ((const int4*)dst)[i];
        d_es[atomicAdd(&d_cur[dv.x], 1)] = sv.x;
        d_es[atomicAdd(&d_cur[dv.y], 1)] = sv.y;
        d_es[atomicAdd(&d_cur[dv.z], 1)] = sv.z;
        d_es[atomicAdd(&d_cur[dv.w], 1)] = sv.w;
    } else {
        int n = i - NE / 4;
        if (n < NN) d_es[atomicAdd(&d_cur[n], 1)] = n;
    }
}

// ---------------- prep kernels ----------------
__global__ void k_cvtA(const float* __restrict__ x) {
    int idx = blockIdx.x * blockDim.x + threadIdx.x;
    if (idx >= NN * IN_DIM / 4) return;
    float4 v = ((const float4*)x)[idx];
    __half2 h0 = __floats2half2_rn(v.x, v.y);
    __half2 h1 = __floats2half2_rn(v.z, v.w);
    uint2 p;
    p.x = *(uint32_t*)&h0;
    p.y = *(uint32_t*)&h1;
    *(uint2*)(d_a16 + (size_t)idx * 4) = p;
}

__global__ void k_prepW(const float* __restrict__ W, int K, int l) {
    int idx = blockIdx.x * blockDim.x + threadIdx.x;
    if (idx >= K * HIDD) return;
    int k = idx / HIDD, n = idx % HIDD;
    d_wh[(size_t)l * HIDD * HIDD + (size_t)n * K + k] = __float2half_rn(W[idx]);
}

// folded BN: g' = gamma*rsqrt(var+eps); c = (bias - mu)*g' + beta
__global__ void k_prepBN(const float* __restrict__ bias, const float* __restrict__ gam,
                         const float* __restrict__ bet, const float* __restrict__ mu,
                         const float* __restrict__ var, int l) {
    int c = threadIdx.x;
    float gs = gam[c] * rsqrtf(var[c] + BN_EPS);
    d_bnS[l * HIDD + c] = gs;
    d_bnC[l * HIDD + c] = (bias[c] - mu[c]) * gs + bet[c];
}

// ---------------- mma helpers ----------------
__device__ __forceinline__ uint32_t cvta_s(const void* p) {
    return (uint32_t)__cvta_generic_to_shared(p);
}
__device__ __forceinline__ void cp16(uint32_t dst, const void* src) {
    asm volatile("cp.async.cg.shared.global [%0], [%1], 16;" :: "r"(dst), "l"(src));
}
__device__ __forceinline__ void mma_f16(float* d, const uint32_t* a, const uint32_t* b) {
    asm volatile(
        "mma.sync.aligned.m16n8k16.row.col.f32.f16.f16.f32 "
        "{%0,%1,%2,%3}, {%4,%5,%6,%7}, {%8,%9}, {%0,%1,%2,%3};"
        : "+f"(d[0]), "+f"(d[1]), "+f"(d[2]), "+f"(d[3])
        : "r"(a[0]), "r"(a[1]), "r"(a[2]), "r"(a[3]), "r"(b[0]), "r"(b[1]));
}
__device__ __forceinline__ void ldm_x4(uint32_t* r, uint32_t addr) {
    asm volatile("ldmatrix.sync.aligned.m8n8.x4.shared.b16 {%0,%1,%2,%3}, [%4];"
                 : "=r"(r[0]), "=r"(r[1]), "=r"(r[2]), "=r"(r[3]) : "r"(addr));
}

__device__ __forceinline__ void stage_load(uint32_t sb, int bm0, int bn0, int K,
                                           int k0, int tid, size_t woff) {
#pragma unroll
    for (int i = 0; i < 4; i++) {
        int gg = tid + i * 256;
        int r = gg >> 3, kk = (gg & 7) * 8;
        uint32_t d = sb + (uint32_t)r * ROWB + (uint32_t)kk * 2;
        size_t soA = (size_t)(bm0 + r) * K + k0 + kk;
        size_t soB = woff + (size_t)(bn0 + r) * K + k0 + kk;
        cp16(d + AO, d_a16 + soA);
        cp16(d + BHO, d_wh + soB);
    }
    asm volatile("cp.async.commit_group;" ::: "memory");
}

// ---------------- fp16 tensor-core GEMM + fused scores ----------------
__global__ void __launch_bounds__(256, 2) k_gemm_mma(int K, int l,
                                                     const float* __restrict__ asrc,
                                                     const float* __restrict__ adst) {
    extern __shared__ char smem[];
    uint32_t sbase = cvta_s(smem);
    int tid = threadIdx.x, w = tid >> 5, lane = tid & 31;
    int bm0 = blockIdx.x * BM, bn0 = blockIdx.y * BN;
    int wm = w >> 1, wn = w & 1;
    int nch = K / BK;
    size_t woff = (size_t)l * HIDD * HIDD;

    float acc[2][8][4];
#pragma unroll
    for (int mt = 0; mt < 2; mt++)
#pragma unroll
        for (int nt = 0; nt < 8; nt++)
#pragma unroll
            for (int j = 0; j < 4; j++) acc[mt][nt][j] = 0.f;

    stage_load(sbase, bm0, bn0, K, 0, tid, woff);

    uint32_t t8 = (uint32_t)(lane >> 3), r8 = (uint32_t)(lane & 7);

    for (int c = 0; c < nch; c++) {
        if (c + 1 < nch) {
            stage_load(sbase + ((c + 1) & 1) * SSZ, bm0, bn0, K, (c + 1) * BK, tid, woff);
            asm volatile("cp.async.wait_group 1;" ::: "memory");
        } else {
            asm volatile("cp.async.wait_group 0;" ::: "memory");
        }
        __syncthreads();

        uint32_t stage = sbase + (c & 1) * SSZ;
#pragma unroll
        for (int ks = 0; ks < 4; ks++) {
            uint32_t kof = (uint32_t)ks * 32 + (t8 >> 1) * 16;
            uint32_t a_f[2][4];
#pragma unroll
            for (int mt = 0; mt < 2; mt++) {
                uint32_t arow = (uint32_t)(wm * 32 + mt * 16) + (t8 & 1) * 8 + r8;
                ldm_x4(a_f[mt], stage + AO + arow * ROWB + kof);
            }
            uint32_t kofb = (uint32_t)ks * 32 + (t8 & 1) * 16;
#pragma unroll
            for (int ntp = 0; ntp < 4; ntp++) {
                uint32_t nrow = (uint32_t)(wn * 64 + ntp * 16) + (t8 >> 1) * 8 + r8;
                uint32_t b_h[4];
                ldm_x4(b_h, stage + BHO + nrow * ROWB + kofb);
#pragma unroll
                for (int mt = 0; mt < 2; mt++) {
                    mma_f16(acc[mt][2 * ntp],     a_f[mt], b_h);
                    mma_f16(acc[mt][2 * ntp + 1], a_f[mt], b_h + 2);
                }
            }
        }
        __syncthreads();
    }

    // ---- fused attention scores ----
    float ss[2][2][2], sd[2][2][2];
#pragma unroll
    for (int mt = 0; mt < 2; mt++)
#pragma unroll
        for (int ro = 0; ro < 2; ro++)
#pragma unroll
            for (int hh = 0; hh < 2; hh++) { ss[mt][ro][hh] = 0.f; sd[mt][ro][hh] = 0.f; }

#pragma unroll
    for (int nt = 0; nt < 8; nt++) {
        int cc = bn0 + wn * 64 + nt * 8 + (lane & 3) * 2;
        float a0s = __ldg(asrc + cc), a1s = __ldg(asrc + cc + 1);
        float a0d = __ldg(adst + cc), a1d = __ldg(adst + cc + 1);
        int hh = nt >> 2;
#pragma unroll
        for (int mt = 0; mt < 2; mt++) {
            ss[mt][0][hh] += acc[mt][nt][0] * a0s + acc[mt][nt][1] * a1s;
            sd[mt][0][hh] += acc[mt][nt][0] * a0d + acc[mt][nt][1] * a1d;
            ss[mt][1][hh] += acc[mt][nt][2] * a0s + acc[mt][nt][3] * a1s;
            sd[mt][1][hh] += acc[mt][nt][2] * a0d + acc[mt][nt][3] * a1d;
        }
    }
#pragma unroll
    for (int mt = 0; mt < 2; mt++)
#pragma unroll
        for (int ro = 0; ro < 2; ro++)
#pragma unroll
            for (int hh = 0; hh < 2; hh++) {
                float vs = ss[mt][ro][hh], vd = sd[mt][ro][hh];
                vs += __shfl_xor_sync(~0u, vs, 1); vs += __shfl_xor_sync(~0u, vs, 2);
                vd += __shfl_xor_sync(~0u, vd, 1); vd += __shfl_xor_sync(~0u, vd, 2);
                if ((lane & 3) == 0) {
                    int r = bm0 + wm * 32 + mt * 16 + (lane >> 2) + ro * 8;
                    int h = (bn0 + wn * 64) / 32 + hh;
                    if (r < NN) {
                        d_ssrc[r * 8 + h] = vs;
                        d_sdst[r * 8 + h] = vd;
                    }
                }
            }

    // ---- write h as fp16 ----
#pragma unroll
    for (int mt = 0; mt < 2; mt++) {
        int r = bm0 + wm * 32 + mt * 16 + (lane >> 2);
#pragma unroll
        for (int nt = 0; nt < 8; nt++) {
            int cc = bn0 + wn * 64 + nt * 8 + (lane & 3) * 2;
            if (r < NN)
                *(__half2*)(d_hf + (size_t)r * 256 + cc) =
                    __floats2half2_rn(acc[mt][nt][0], acc[mt][nt][1]);
            if (r + 8 < NN)
                *(__half2*)(d_hf + (size_t)(r + 8) * 256 + cc) =
                    __floats2half2_rn(acc[mt][nt][2], acc[mt][nt][3]);
        }
    }
}

__device__ __forceinline__ float leaky(float x) { return x > 0.f ? x : NEG_SLOPE * x; }

// ---------------- aggregation (1 warp / node), single pass, 8-deep pipeline ----------------
__global__ void __launch_bounds__(128) k_agg(int l, int useRes) {
    int warp = (blockIdx.x * blockDim.x + threadIdx.x) >> 5;
    int lane = threadIdx.x & 31;
    if (warp >= NN) return;
    int n = warp;
    int beg = d_off[n], end = d_off[n + 1];
    int h = lane >> 2;

    float my_sd = __ldg(d_sdst + n * 8 + h);

    const uint4* hf4 = (const uint4*)d_hf;
    float acc[8] = {0.f, 0.f, 0.f, 0.f, 0.f, 0.f, 0.f, 0.f};
    float z = 0.f;
    int e0 = beg;
    for (; e0 + 8 <= end; e0 += 8) {
        int s[8];
#pragma unroll
        for (int j = 0; j < 8; j++) s[j] = d_es[e0 + j];
        float sv[8];
#pragma unroll
        for (int j = 0; j < 8; j++) sv[j] = __ldg(d_ssrc + s[j] * 8 + h);
        uint4 v[8];
#pragma unroll
        for (int j = 0; j < 8; j++) v[j] = __ldg(hf4 + (size_t)s[j] * 32 + lane);
        float cf[8];
#pragma unroll
        for (int j = 0; j < 8; j++) {
            cf[j] = __expf(leaky(sv[j] + my_sd));
            z += cf[j];
        }
#pragma unroll
        for (int j = 0; j < 8; j++) {
            float coef = cf[j];
            float2 f0 = __half22float2(*(const __half2*)&v[j].x);
            float2 f1 = __half22float2(*(const __half2*)&v[j].y);
            float2 f2 = __half22float2(*(const __half2*)&v[j].z);
            float2 f3 = __half22float2(*(const __half2*)&v[j].w);
            acc[0] += f0.x * coef; acc[1] += f0.y * coef;
            acc[2] += f1.x * coef; acc[3] += f1.y * coef;
            acc[4] += f2.x * coef; acc[5] += f2.y * coef;
            acc[6] += f3.x * coef; acc[7] += f3.y * coef;
        }
    }
    for (; e0 < end; e0++) {
        int s = d_es[e0];
        float sv = __ldg(d_ssrc + s * 8 + h);
        float coef = __expf(leaky(sv + my_sd));
        z += coef;
        uint4 v = __ldg(hf4 + (size_t)s * 32 + lane);
        float2 f0 = __half22float2(*(const __half2*)&v.x);
        float2 f1 = __half22float2(*(const __half2*)&v.y);
        float2 f2 = __half22float2(*(const __half2*)&v.z);
        float2 f3 = __half22float2(*(const __half2*)&v.w);
        acc[0] += f0.x * coef; acc[1] += f0.y * coef;
        acc[2] += f1.x * coef; acc[3] += f1.y * coef;
        acc[4] += f2.x * coef; acc[5] += f2.y * coef;
        acc[6] += f3.x * coef; acc[7] += f3.y * coef;
    }
    float inv = 1.f / (z + 1e-16f);
#pragma unroll
    for (int j = 0; j < 8; j++) acc[j] *= inv;

    // epilogue: cols col..col+7, folded BN (acc*gs + gc) + residual(fp16) + ELU
    int col = lane * 8;
    float4 s0 = *(const float4*)(d_bnS + l * HIDD + col);
    float4 s1 = *(const float4*)(d_bnS + l * HIDD + col + 4);
    float4 c0 = *(const float4*)(d_bnC + l * HIDD + col);
    float4 c1 = *(const float4*)(d_bnC + l * HIDD + col + 4);
    float gs[8] = {s0.x, s0.y, s0.z, s0.w, s1.x, s1.y, s1.z, s1.w};
    float gc[8] = {c0.x, c0.y, c0.z, c0.w, c1.x, c1.y, c1.z, c1.w};
    float rr[8] = {0.f, 0.f, 0.f, 0.f, 0.f, 0.f, 0.f, 0.f};
    if (useRes) {
        uint4 rv = *(const uint4*)(d_a16 + (size_t)n * 256 + col);
        float2 r0 = __half22float2(*(const __half2*)&rv.x);
        float2 r1 = __half22float2(*(const __half2*)&rv.y);
        float2 r2 = __half22float2(*(const __half2*)&rv.z);
        float2 r3 = __half22float2(*(const __half2*)&rv.w);
        rr[0] = r0.x; rr[1] = r0.y; rr[2] = r1.x; rr[3] = r1.y;
        rr[4] = r2.x; rr[5] = r2.y; rr[6] = r3.x; rr[7] = r3.y;
    }
    float outv[8];
#pragma unroll
    for (int j = 0; j < 8; j++) {
        float v = acc[j] * gs[j] + gc[j];
        if (useRes) v += rr[j];
        outv[j] = v > 0.f ? v : (__expf(v) - 1.0f);
    }

    __half2 q0 = __floats2half2_rn(outv[0], outv[1]);
    __half2 q1 = __floats2half2_rn(outv[2], outv[3]);
    __half2 q2 = __floats2half2_rn(outv[4], outv[5]);
    __half2 q3 = __floats2half2_rn(outv[6], outv[7]);
    uint4 pk;
    pk.x = *(uint32_t*)&q0; pk.y = *(uint32_t*)&q1;
    pk.z = *(uint32_t*)&q2; pk.w = *(uint32_t*)&q3;
    *(uint4*)(d_a16 + (size_t)n * 256 + col) = pk;
}

// ---------------- pooling + output heads (reads fp16 activations) ----------------
__device__ __forceinline__ int lbound(const int* __restrict__ a, int n, int v) {
    int lo = 0, hi = n;
    while (lo < hi) {
        int mid = (lo + hi) >> 1;
        if (a[mid] < v) lo = mid + 1; else hi = mid;
    }
    return lo;
}

__global__ void k_pool(const int* __restrict__ batch,
                       const float* __restrict__ ow0, const float* __restrict__ ob0,
                       const float* __restrict__ ow1, const float* __restrict__ ob1,
                       float* __restrict__ out) {
    int g = blockIdx.x;
    int t = threadIdx.x;
    int lo = lbound(batch, NN, g);
    int hi = lbound(batch, NN, g + 1);
    __shared__ float pooled[3 * HIDD];
    __shared__ float sacc[6];

    int c = t;
    float sum = 0.f, mx = -1e30f;
    for (int n = lo; n < hi; n++) {
        float v = __half2float(d_a16[(size_t)n * 256 + c]);
        sum += v;
        mx = fmaxf(mx, v);
    }
    int cnt = hi - lo;
    pooled[c]       = sum / fmaxf((float)cnt, 1.f);
    pooled[256 + c] = sum;
    pooled[512 + c] = (cnt > 0) ? mx : 0.f;
    if (t < 6) sacc[t] = 0.f;
    __syncthreads();

    float p0[3] = {0.f, 0.f, 0.f}, p1[3] = {0.f, 0.f, 0.f};
    for (int j = t; j < 768; j += 256) {
        float v = pooled[j];
#pragma unroll
        for (int k = 0; k < 3; k++) {
            p0[k] += v * ow0[j * 3 + k];
            p1[k] += v * ow1[j * 3 + k];
        }
    }
#pragma unroll
    for (int k = 0; k < 3; k++) {
        atomicAdd(&sacc[k], p0[k]);
        atomicAdd(&sacc[3 + k], p1[k]);
    }
    __syncthreads();
    if (t < 3) {
        out[g * 3 + t]          = sacc[t]     + ob0[t];
        out[GG * 3 + g * 3 + t] = sacc[3 + t] + ob1[t];
    }
}

// ---------------- launch ----------------
extern "C" void kernel_launch(void* const* d_in, const int* in_sizes, int n_in,
                              void* d_out, int out_size) {
    const float* x     = (const float*)d_in[0];
    const int*   ei    = (const int*)d_in[1];
    const int*   batch = (const int*)d_in[2];

    const float* W[3]  = {(const float*)d_in[3],  (const float*)d_in[11], (const float*)d_in[19]};
    const float* AS[3] = {(const float*)d_in[4],  (const float*)d_in[12], (const float*)d_in[20]};
    const float* AD[3] = {(const float*)d_in[5],  (const float*)d_in[13], (const float*)d_in[21]};
    const float* BI[3] = {(const float*)d_in[6],  (const float*)d_in[14], (const float*)d_in[22]};
    const float* GA[3] = {(const float*)d_in[7],  (const float*)d_in[15], (const float*)d_in[23]};
    const float* BE[3] = {(const float*)d_in[8],  (const float*)d_in[16], (const float*)d_in[24]};
    const float* MU[3] = {(const float*)d_in[9],  (const float*)d_in[17], (const float*)d_in[25]};
    const float* VA[3] = {(const float*)d_in[10], (const float*)d_in[18], (const float*)d_in[26]};
    const float* ow0 = (const float*)d_in[27];
    const float* ob0 = (const float*)d_in[28];
    const float* ow1 = (const float*)d_in[29];
    const float* ob1 = (const float*)d_in[30];
    float* out = (float*)d_out;

    static cudaStream_t s2 = nullptr;
    static cudaEvent_t evA = nullptr, evB = nullptr;
    if (!s2) {
        cudaFuncSetAttribute(k_gemm_mma, cudaFuncAttributeMaxDynamicSharedMemorySize,
                             SMEM_TOTAL);
        cudaStreamCreateWithFlags(&s2, cudaStreamNonBlocking);
        cudaEventCreateWithFlags(&evA, cudaEventDisableTiming);
        cudaEventCreateWithFlags(&evB, cudaEventDisableTiming);
    }

    // Fork: CSR build + layer-2/3 weight prep + BN folds on s2, overlapped with
    // the critical path (prepW0 + cvtA + GEMM layer 1) on the main stream.
    cudaEventRecord(evA, 0);
    cudaStreamWaitEvent(s2, evA, 0);
    k_init_deg<<<cdiv(NN, 256), 256, 0, s2>>>();
    k_count<<<cdiv(NE / 4, 256), 256, 0, s2>>>(ei + NE);
    k_scan<<<1, 1024, 0, s2>>>();
    k_scatter<<<cdiv(NE / 4 + NN, 256), 256, 0, s2>>>(ei, ei + NE);
    k_prepW<<<cdiv(HIDD * HIDD, 256), 256, 0, s2>>>(W[1], HIDD, 1);
    k_prepW<<<cdiv(HIDD * HIDD, 256), 256, 0, s2>>>(W[2], HIDD, 2);
    k_prepBN<<<1, 256, 0, s2>>>(BI[0], GA[0], BE[0], MU[0], VA[0], 0);
    k_prepBN<<<1, 256, 0, s2>>>(BI[1], GA[1], BE[1], MU[1], VA[1], 1);
    k_prepBN<<<1, 256, 0, s2>>>(BI[2], GA[2], BE[2], MU[2], VA[2], 2);
    cudaEventRecord(evB, s2);

    k_prepW<<<cdiv(IN_DIM * HIDD, 256), 256>>>(W[0], IN_DIM, 0);
    k_cvtA<<<cdiv(NN * IN_DIM / 4, 256), 256>>>(x);

    dim3 gg(NTILES, 2);
    k_gemm_mma<<<gg, 256, SMEM_TOTAL>>>(IN_DIM, 0, AS[0], AD[0]);

    // Join: aggregation needs CSR + BN folds (later GEMMs need W1/W2).
    cudaStreamWaitEvent(0, evB, 0);

    k_agg<<<cdiv(NN, 4), 128>>>(0, 0);
    for (int l = 1; l < 3; l++) {
        k_gemm_mma<<<gg, 256, SMEM_TOTAL>>>(HIDD, l, AS[l], AD[l]);
        k_agg<<<cdiv(NN, 4), 128>>>(l, 1);
    }
    k_pool<<<GG, 256>>>(batch, ow0, ob0, ow1, ob1, out);
}